// round 12
// baseline (speedup 1.0000x reference)
#include <cuda_runtime.h>
#include <cuda_fp16.h>
#include <cstdint>

#define BB 512
#define DD 256
#define S_SCALE 30.0f
#define MARGIN 0.2f
#define EXPC 43.2808512f          // 30 * log2(e)

// -------- device scratch --------
__device__ __half g_xn[BB * DD];     // normalized X, fp16
__device__ float g_sumexp[BB];
__device__ float g_cost[BB];
__device__ int   g_targets[BB];

// ---------------- helpers ----------------
__device__ __forceinline__ uint32_t smem_u32(const void* p) {
    uint32_t a;
    asm("{ .reg .u64 t; cvta.to.shared.u64 t, %1; cvt.u32.u64 %0, t; }"
        : "=r"(a) : "l"(p));
    return a;
}

#define CP16F(sa, ga) \
    asm volatile("cp.async.cg.shared.global [%0], [%1], 16;" \
                 :: "r"(sa), "l"(ga) : "memory")
#define CP_COMMIT() asm volatile("cp.async.commit_group;" ::: "memory")
#define CP_WAIT1()  asm volatile("cp.async.wait_group 1;" ::: "memory")
#define CP_WAIT0()  asm volatile("cp.async.wait_group 0;" ::: "memory")

#define LDSM4(r0, r1, r2, r3, addr) \
    asm volatile("ldmatrix.sync.aligned.m8n8.x4.shared.b16 {%0,%1,%2,%3}, [%4];" \
                 : "=r"(r0), "=r"(r1), "=r"(r2), "=r"(r3) : "r"(addr))

// fp16-accumulator HMMA
__device__ __forceinline__ void mma16816h(uint32_t* d, const uint32_t* a,
                                          uint32_t b0, uint32_t b1) {
    asm volatile(
        "mma.sync.aligned.m16n8k16.row.col.f16.f16.f16.f16 "
        "{%0,%1}, {%2,%3,%4,%5}, {%6,%7}, {%0,%1};\n"
        : "+r"(d[0]), "+r"(d[1])
        : "r"(a[0]), "r"(a[1]), "r"(a[2]), "r"(a[3]), "r"(b0), "r"(b1));
}

__device__ __forceinline__ uint32_t pack_h2(float x, float y) {
    __half2 h = __floats2half2_rn(x, y);
    return *reinterpret_cast<uint32_t*>(&h);
}
__device__ __forceinline__ float2 h2_to_f2(uint32_t u) {
    __half2 h;
    *reinterpret_cast<uint32_t*>(&h) = u;
    return __half22float2(h);
}

// SW128 blocked-atom tile: 128 rows x 256 fp16 (32 chunks of 16B per row).
__device__ __forceinline__ uint32_t tile_off(int r, int cc) {
    return (uint32_t)(((r >> 3) + (cc >> 3) * 16) * 1024
                    + (r & 7) * 128 + ((((cc & 7) * 16) ^ ((r & 7) << 4))));
}

// ---------------------------------------------------------
// prep + X normalize (merged).
__global__ void prep_norm_kernel(const float* __restrict__ in,
                                 const int* __restrict__ t32) {
    if (blockIdx.x == 0) {
        __shared__ int flag;
        int i = threadIdx.x;  // 256 threads
        if (i == 0) flag = 0;
        __syncthreads();
        if (t32[2 * i + 1] != 0) flag = 1;   // odd words of first 512
        __syncthreads();
#pragma unroll
        for (int k = 0; k < 2; k++) {
            int j = i + 256 * k;
            g_targets[j] = flag ? t32[j] : (int)((const long long*)t32)[j];
            g_sumexp[j] = 0.0f;
        }
    }
    int row = blockIdx.x * 8 + (threadIdx.x >> 5);
    int lane = threadIdx.x & 31;
    const float4* p = (const float4*)(in + (size_t)row * DD);
    float4 v0 = p[lane];
    float4 v1 = p[lane + 32];
    float s = v0.x * v0.x + v0.y * v0.y + v0.z * v0.z + v0.w * v0.w
            + v1.x * v1.x + v1.y * v1.y + v1.z * v1.z + v1.w * v1.w;
#pragma unroll
    for (int o = 16; o; o >>= 1) s += __shfl_xor_sync(0xffffffffu, s, o);
    float inv = rsqrtf(s);
    unsigned* q = (unsigned*)(g_xn + (size_t)row * DD);
    q[2 * lane + 0]        = pack_h2(v0.x * inv, v0.y * inv);
    q[2 * lane + 1]        = pack_h2(v0.z * inv, v0.w * inv);
    q[2 * (lane + 32) + 0] = pack_h2(v1.x * inv, v1.y * inv);
    q[2 * (lane + 32) + 1] = pack_h2(v1.z * inv, v1.w * inv);
}

// ---------------------------------------------------------
// exact fp32 target cosine
__global__ void cost_kernel(const float* __restrict__ W,
                            const float* __restrict__ X) {
    int b = blockIdx.x * 8 + (threadIdx.x >> 5);
    int lane = threadIdx.x & 31;
    int c = g_targets[b];
    const float4* wr = (const float4*)(W + (size_t)c * DD);
    const float4* xr = (const float4*)(X + (size_t)b * DD);
    float dxx = 0.f, dww = 0.f, dxw = 0.f;
#pragma unroll
    for (int h = 0; h < 2; h++) {
        float4 w = wr[lane + 32 * h];
        float4 x = xr[lane + 32 * h];
        dww += w.x * w.x + w.y * w.y + w.z * w.z + w.w * w.w;
        dxx += x.x * x.x + x.y * x.y + x.z * x.z + x.w * x.w;
        dxw += w.x * x.x + w.y * x.y + w.z * x.z + w.w * x.w;
    }
#pragma unroll
    for (int o = 16; o; o >>= 1) {
        dxx += __shfl_xor_sync(0xffffffffu, dxx, o);
        dww += __shfl_xor_sync(0xffffffffu, dww, o);
        dxw += __shfl_xor_sync(0xffffffffu, dxw, o);
    }
    if (lane == 0) g_cost[b] = dxw * rsqrtf(dxx * dww);
}

// ---------------------------------------------------------
// GEMM + exp-sum, 512 threads (16 warps, 4m x 4n), fp16 in/acc.
#define SM_W   0
#define SM_X0  65536
#define SM_X1  131072
#define SM_TOTAL 196608
#define NT 512

__global__ __launch_bounds__(NT, 1) void gemm_sumexp_kernel(
        const float* __restrict__ W, int C) {
    extern __shared__ char smem[];
    const uint32_t sb = smem_u32(smem);
    const int tid = threadIdx.x, wid = tid >> 5, lane = tid & 31;
    const int cbase = blockIdx.x * 128;
    const char* xsrc = (const char*)g_xn;

    // prefetch X blocks 0,1 (async): 4096 chunks each, 8 per thread
#pragma unroll
    for (int it = 0; it < 8; it++) {
        int i = tid + NT * it, r = i >> 5, cc = i & 31;
        CP16F(sb + SM_X0 + tile_off(r, cc), xsrc + ((size_t)r * 32 + cc) * 16);
    }
    CP_COMMIT();
#pragma unroll
    for (int it = 0; it < 8; it++) {
        int i = tid + NT * it, r = i >> 5, cc = i & 31;
        CP16F(sb + SM_X1 + tile_off(r, cc), xsrc + ((size_t)(128 + r) * 32 + cc) * 16);
    }
    CP_COMMIT();

    // fused W normalization -> fp16: 4 threads per row (quarters), 2-pass via L1
    {
        int r = tid >> 2, h = tid & 3;
        int cg = cbase + r;
        bool ok = (cg < C);
        const float4* wrow =
            (const float4*)(W + (size_t)(ok ? cg : cbase) * DD) + h * 16;
        float ss = 0.f;
#pragma unroll 4
        for (int i = 0; i < 16; i++) {
            float4 v = wrow[i];
            ss += v.x * v.x + v.y * v.y + v.z * v.z + v.w * v.w;
        }
        ss += __shfl_xor_sync(0xffffffffu, ss, 1);
        ss += __shfl_xor_sync(0xffffffffu, ss, 2);
        float inv = ok ? rsqrtf(ss) : 0.f;
#pragma unroll 2
        for (int k = 0; k < 8; k++) {
            float4 a = wrow[2 * k];        // L1 hit
            float4 d = wrow[2 * k + 1];
            uint4 u;
            u.x = pack_h2(a.x * inv, a.y * inv);
            u.y = pack_h2(a.z * inv, a.w * inv);
            u.z = pack_h2(d.x * inv, d.y * inv);
            u.w = pack_h2(d.z * inv, d.w * inv);
            *(uint4*)(smem + SM_W + tile_off(r, h * 8 + k)) = u;
        }
    }
    CP_WAIT1();        // X0 resident; X1 in flight
    __syncthreads();

    const int wm = wid & 3, wn = wid >> 2;
    const int m0 = wm * 32, n0 = wn * 32;
    const int a_rl   = ((lane >> 3) & 1) * 8 + (lane & 7);
    const int a_cchi = (lane >> 4) & 1;
    const int b_rl   = ((lane >> 4) & 1) * 8 + (lane & 7);
    const int b_cchi = (lane >> 3) & 1;
    const uint32_t wa = sb + SM_W;

    for (int b = 0; b < 4; b++) {
        const uint32_t xa = sb + ((b & 1) ? SM_X1 : SM_X0);

        uint32_t acc[2][4][2];   // fp16x2 accumulators
#pragma unroll
        for (int i = 0; i < 2; i++)
#pragma unroll
            for (int j = 0; j < 4; j++) {
                acc[i][j][0] = 0u;
                acc[i][j][1] = 0u;
            }

#pragma unroll
        for (int s = 0; s < 16; s++) {
            uint32_t afr[2][4];
#pragma unroll
            for (int i = 0; i < 2; i++) {
                int r = m0 + 16 * i + a_rl, cc = 2 * s + a_cchi;
                LDSM4(afr[i][0], afr[i][1], afr[i][2], afr[i][3],
                      xa + tile_off(r, cc));
            }
            uint32_t bfr[2][4];
#pragma unroll
            for (int j4 = 0; j4 < 2; j4++) {
                int r = n0 + 16 * j4 + b_rl, cc = 2 * s + b_cchi;
                LDSM4(bfr[j4][0], bfr[j4][1], bfr[j4][2], bfr[j4][3],
                      wa + tile_off(r, cc));
            }
#pragma unroll
            for (int j = 0; j < 4; j++) {
                uint32_t b0 = bfr[j >> 1][(j & 1) * 2];
                uint32_t b1 = bfr[j >> 1][(j & 1) * 2 + 1];
                mma16816h(acc[0][j], afr[0], b0, b1);
                mma16816h(acc[1][j], afr[1], b0, b1);
            }
        }

        // epilogue: unpack fp16 pairs, exp2, per-row reduce
        float rs[4] = {0.f, 0.f, 0.f, 0.f};
#pragma unroll
        for (int i = 0; i < 2; i++)
#pragma unroll
            for (int j = 0; j < 4; j++) {
                float2 c0 = h2_to_f2(acc[i][j][0]);   // row m0+16i+g
                float2 c1 = h2_to_f2(acc[i][j][1]);   // row m0+16i+g+8
                rs[2 * i]     += exp2f(fmaf(EXPC, c0.x, -EXPC))
                               + exp2f(fmaf(EXPC, c0.y, -EXPC));
                rs[2 * i + 1] += exp2f(fmaf(EXPC, c1.x, -EXPC))
                               + exp2f(fmaf(EXPC, c1.y, -EXPC));
            }
#pragma unroll
        for (int q = 0; q < 4; q++) {
            rs[q] += __shfl_xor_sync(0xffffffffu, rs[q], 1);
            rs[q] += __shfl_xor_sync(0xffffffffu, rs[q], 2);
        }
        if ((lane & 3) == 0) {
            int rbase = b * 128 + m0 + (lane >> 2);
#pragma unroll
            for (int q = 0; q < 4; q++)
                atomicAdd(&g_sumexp[rbase + (q >> 1) * 16 + (q & 1) * 8], rs[q]);
        }

        __syncthreads();   // everyone done reading buf[b&1]
        if (b < 2) {
            uint32_t dst = sb + ((b & 1) ? SM_X1 : SM_X0);
#pragma unroll
            for (int it = 0; it < 8; it++) {
                int i = tid + NT * it, r = i >> 5, cc = i & 31;
                CP16F(dst + tile_off(r, cc),
                      xsrc + ((size_t)((b + 2) * 128 + r) * 32 + cc) * 16);
            }
            CP_COMMIT();
            CP_WAIT1();
        } else if (b == 2) {
            CP_WAIT0();
        }
        __syncthreads();
    }
}

// ---------------------------------------------------------
// finalize: pad removal, margin correction (exact cosine), lse, mean
__global__ void finalize_kernel(float* __restrict__ out, int npad) {
    __shared__ double sd[BB];
    int b = threadIdx.x;
    float ct = g_cost[b];
    float lt = S_SCALE * (ct - MARGIN);
    float s = g_sumexp[b] - (float)npad * expf(-30.0f)
            + __expf(lt - 30.0f) - __expf(S_SCALE * ct - 30.0f);
    float nll = 30.0f + logf(s) - lt;
    sd[b] = (double)nll;
    __syncthreads();
    for (int o = 256; o; o >>= 1) {
        if (b < o) sd[b] += sd[b + o];
        __syncthreads();
    }
    if (b == 0) out[0] = (float)(sd[0] / (double)BB);
}

// ---------------------------------------------------------
extern "C" void kernel_launch(void* const* d_in, const int* in_sizes, int n_in,
                              void* d_out, int out_size) {
    const float* inputs  = (const float*)d_in[0];
    const float* weight  = (const float*)d_in[1];
    const int*   targets = (const int*)d_in[2];
    float* out = (float*)d_out;

    int C = in_sizes[1] / DD;
    int gridC = (C + 127) / 128;
    int npad = gridC * 128 - C;

    cudaFuncSetAttribute(gemm_sumexp_kernel,
                         cudaFuncAttributeMaxDynamicSharedMemorySize, SM_TOTAL);

    prep_norm_kernel<<<BB / 8, 256>>>(inputs, targets);
    cost_kernel<<<BB / 8, 256>>>(weight, inputs);
    gemm_sumexp_kernel<<<gridC, NT, SM_TOTAL>>>(weight, C);
    finalize_kernel<<<1, BB>>>(out, npad);
}

// round 13
// speedup vs baseline: 1.1917x; 1.1917x over previous
#include <cuda_runtime.h>
#include <cuda_fp16.h>
#include <cstdint>

#define BB 512
#define DD 256
#define S_SCALE 30.0f
#define MARGIN 0.2f
#define EXPC 43.2808512f          // 30 * log2(e)

// -------- device scratch --------
__device__ __half g_xn[BB * DD];     // normalized X, fp16
__device__ float g_sumexp[BB];
__device__ float g_cost[BB];
__device__ unsigned g_done;

// ---------------- helpers ----------------
__device__ __forceinline__ uint32_t smem_u32(const void* p) {
    uint32_t a;
    asm("{ .reg .u64 t; cvta.to.shared.u64 t, %1; cvt.u32.u64 %0, t; }"
        : "=r"(a) : "l"(p));
    return a;
}

#define CP16F(sa, ga) \
    asm volatile("cp.async.cg.shared.global [%0], [%1], 16;" \
                 :: "r"(sa), "l"(ga) : "memory")
#define CP_COMMIT() asm volatile("cp.async.commit_group;" ::: "memory")
#define CP_WAIT1()  asm volatile("cp.async.wait_group 1;" ::: "memory")
#define CP_WAIT0()  asm volatile("cp.async.wait_group 0;" ::: "memory")

#define LDSM4(r0, r1, r2, r3, addr) \
    asm volatile("ldmatrix.sync.aligned.m8n8.x4.shared.b16 {%0,%1,%2,%3}, [%4];" \
                 : "=r"(r0), "=r"(r1), "=r"(r2), "=r"(r3) : "r"(addr))

// fp16-accumulator HMMA
__device__ __forceinline__ void mma16816h(uint32_t* d, const uint32_t* a,
                                          uint32_t b0, uint32_t b1) {
    asm volatile(
        "mma.sync.aligned.m16n8k16.row.col.f16.f16.f16.f16 "
        "{%0,%1}, {%2,%3,%4,%5}, {%6,%7}, {%0,%1};\n"
        : "+r"(d[0]), "+r"(d[1])
        : "r"(a[0]), "r"(a[1]), "r"(a[2]), "r"(a[3]), "r"(b0), "r"(b1));
}

__device__ __forceinline__ uint32_t pack_h2(float x, float y) {
    __half2 h = __floats2half2_rn(x, y);
    return *reinterpret_cast<uint32_t*>(&h);
}
__device__ __forceinline__ float2 h2_to_f2(uint32_t u) {
    __half2 h;
    *reinterpret_cast<uint32_t*>(&h) = u;
    return __half22float2(h);
}

// SW128 blocked-atom tile: 128 rows x 256 fp16 (32 chunks of 16B per row).
__device__ __forceinline__ uint32_t tile_off(int r, int cc) {
    return (uint32_t)(((r >> 3) + (cc >> 3) * 16) * 1024
                    + (r & 7) * 128 + ((((cc & 7) * 16) ^ ((r & 7) << 4))));
}

// ---------------------------------------------------------
// merged prep: blocks 0-63 normalize X (8 rows each; block 0 zeros accums
// and the done ticket); blocks 64-127 compute exact fp32 target cosines.
__global__ void prep_cost_kernel(const float* __restrict__ in,
                                 const float* __restrict__ W,
                                 const int* __restrict__ t32) {
    int wid = threadIdx.x >> 5, lane = threadIdx.x & 31;
    if (blockIdx.x < 64) {
        if (blockIdx.x == 0) {
            int i = threadIdx.x;
            g_sumexp[i] = 0.0f;
            g_sumexp[i + 256] = 0.0f;
            if (i == 0) g_done = 0u;
        }
        int row = blockIdx.x * 8 + wid;
        const float4* p = (const float4*)(in + (size_t)row * DD);
        float4 v0 = p[lane];
        float4 v1 = p[lane + 32];
        float s = v0.x * v0.x + v0.y * v0.y + v0.z * v0.z + v0.w * v0.w
                + v1.x * v1.x + v1.y * v1.y + v1.z * v1.z + v1.w * v1.w;
#pragma unroll
        for (int o = 16; o; o >>= 1) s += __shfl_xor_sync(0xffffffffu, s, o);
        float inv = rsqrtf(s);
        unsigned* q = (unsigned*)(g_xn + (size_t)row * DD);
        q[2 * lane + 0]        = pack_h2(v0.x * inv, v0.y * inv);
        q[2 * lane + 1]        = pack_h2(v0.z * inv, v0.w * inv);
        q[2 * (lane + 32) + 0] = pack_h2(v1.x * inv, v1.y * inv);
        q[2 * (lane + 32) + 1] = pack_h2(v1.z * inv, v1.w * inv);
    } else {
        // dtype decode: int64 little-endian => odd 32-bit words all zero
        __shared__ int flag;
        if (threadIdx.x == 0) flag = 0;
        __syncthreads();
        if (t32[2 * threadIdx.x + 1] != 0) flag = 1;   // racy OR, fine
        __syncthreads();
        int b = (blockIdx.x - 64) * 8 + wid;
        int c = flag ? t32[b] : (int)((const long long*)t32)[b];
        const float4* wr = (const float4*)(W + (size_t)c * DD);
        const float4* xr = (const float4*)(in + (size_t)b * DD);
        float dxx = 0.f, dww = 0.f, dxw = 0.f;
#pragma unroll
        for (int h = 0; h < 2; h++) {
            float4 w = wr[lane + 32 * h];
            float4 x = xr[lane + 32 * h];
            dww += w.x * w.x + w.y * w.y + w.z * w.z + w.w * w.w;
            dxx += x.x * x.x + x.y * x.y + x.z * x.z + x.w * x.w;
            dxw += w.x * x.x + w.y * x.y + w.z * x.z + w.w * x.w;
        }
#pragma unroll
        for (int o = 16; o; o >>= 1) {
            dxx += __shfl_xor_sync(0xffffffffu, dxx, o);
            dww += __shfl_xor_sync(0xffffffffu, dww, o);
            dxw += __shfl_xor_sync(0xffffffffu, dxw, o);
        }
        if (lane == 0) g_cost[b] = dxw * rsqrtf(dxx * dww);
    }
}

// ---------------------------------------------------------
// GEMM + exp-sum (R9 mainloop) + done-ticket fused finalize.
#define SM_W   0
#define SM_X0  65536
#define SM_X1  131072
#define SM_TOTAL 196608

__global__ __launch_bounds__(256, 1) void gemm_sumexp_kernel(
        const float* __restrict__ W, float* __restrict__ out,
        int C, int npad) {
    extern __shared__ char smem[];
    const uint32_t sb = smem_u32(smem);
    const int tid = threadIdx.x, wid = tid >> 5, lane = tid & 31;
    const int cbase = blockIdx.x * 128;
    const char* xsrc = (const char*)g_xn;

    // prefetch X blocks 0,1 (async): 4096 chunks each, 16 per thread
#pragma unroll
    for (int it = 0; it < 16; it++) {
        int i = tid + 256 * it, r = i >> 5, cc = i & 31;
        CP16F(sb + SM_X0 + tile_off(r, cc), xsrc + ((size_t)r * 32 + cc) * 16);
    }
    CP_COMMIT();
#pragma unroll
    for (int it = 0; it < 16; it++) {
        int i = tid + 256 * it, r = i >> 5, cc = i & 31;
        CP16F(sb + SM_X1 + tile_off(r, cc), xsrc + ((size_t)(128 + r) * 32 + cc) * 16);
    }
    CP_COMMIT();

    // fused W normalization -> fp16: 2 threads per row (halves), 2-pass via L1
    {
        int r = tid >> 1, h = tid & 1;
        int cg = cbase + r;
        bool ok = (cg < C);
        const float4* wrow =
            (const float4*)(W + (size_t)(ok ? cg : cbase) * DD) + h * 32;
        float ss = 0.f;
#pragma unroll
        for (int i = 0; i < 32; i++) {
            float4 v = wrow[i];
            ss += v.x * v.x + v.y * v.y + v.z * v.z + v.w * v.w;
        }
        ss += __shfl_xor_sync(0xffffffffu, ss, 1);
        float inv = ok ? rsqrtf(ss) : 0.f;
#pragma unroll
        for (int i = 0; i < 16; i++) {
            float4 a = wrow[2 * i];        // L1 hit
            float4 d = wrow[2 * i + 1];
            uint4 u;
            u.x = pack_h2(a.x * inv, a.y * inv);
            u.y = pack_h2(a.z * inv, a.w * inv);
            u.z = pack_h2(d.x * inv, d.y * inv);
            u.w = pack_h2(d.z * inv, d.w * inv);
            *(uint4*)(smem + SM_W + tile_off(r, h * 16 + i)) = u;
        }
    }
    CP_WAIT1();        // X0 resident; X1 in flight
    __syncthreads();

    const int wm = wid & 3, wn = wid >> 2;
    const int m0 = wm * 32, n0 = wn * 64;
    const int a_rl   = ((lane >> 3) & 1) * 8 + (lane & 7);
    const int a_cchi = (lane >> 4) & 1;
    const int b_rl   = ((lane >> 4) & 1) * 8 + (lane & 7);
    const int b_cchi = (lane >> 3) & 1;
    const uint32_t wa = sb + SM_W;

    for (int b = 0; b < 4; b++) {
        const uint32_t xa = sb + ((b & 1) ? SM_X1 : SM_X0);

        uint32_t acc[2][8][2];   // fp16x2 accumulators
#pragma unroll
        for (int i = 0; i < 2; i++)
#pragma unroll
            for (int j = 0; j < 8; j++) {
                acc[i][j][0] = 0u;
                acc[i][j][1] = 0u;
            }

#pragma unroll
        for (int s = 0; s < 16; s++) {
            uint32_t afr[2][4];
#pragma unroll
            for (int i = 0; i < 2; i++) {
                int r = m0 + 16 * i + a_rl, cc = 2 * s + a_cchi;
                LDSM4(afr[i][0], afr[i][1], afr[i][2], afr[i][3],
                      xa + tile_off(r, cc));
            }
            uint32_t bfr[4][4];
#pragma unroll
            for (int j4 = 0; j4 < 4; j4++) {
                int r = n0 + 16 * j4 + b_rl, cc = 2 * s + b_cchi;
                LDSM4(bfr[j4][0], bfr[j4][1], bfr[j4][2], bfr[j4][3],
                      wa + tile_off(r, cc));
            }
#pragma unroll
            for (int j = 0; j < 8; j++) {
                uint32_t b0 = bfr[j >> 1][(j & 1) * 2];
                uint32_t b1 = bfr[j >> 1][(j & 1) * 2 + 1];
                mma16816h(acc[0][j], afr[0], b0, b1);
                mma16816h(acc[1][j], afr[1], b0, b1);
            }
        }

        // epilogue: unpack fp16 pairs, exp2, per-row reduce
        float rs[4] = {0.f, 0.f, 0.f, 0.f};
#pragma unroll
        for (int i = 0; i < 2; i++)
#pragma unroll
            for (int j = 0; j < 8; j++) {
                float2 c0 = h2_to_f2(acc[i][j][0]);
                float2 c1 = h2_to_f2(acc[i][j][1]);
                rs[2 * i]     += exp2f(fmaf(EXPC, c0.x, -EXPC))
                               + exp2f(fmaf(EXPC, c0.y, -EXPC));
                rs[2 * i + 1] += exp2f(fmaf(EXPC, c1.x, -EXPC))
                               + exp2f(fmaf(EXPC, c1.y, -EXPC));
            }
#pragma unroll
        for (int q = 0; q < 4; q++) {
            rs[q] += __shfl_xor_sync(0xffffffffu, rs[q], 1);
            rs[q] += __shfl_xor_sync(0xffffffffu, rs[q], 2);
        }
        if ((lane & 3) == 0) {
            int rbase = b * 128 + m0 + (lane >> 2);
#pragma unroll
            for (int q = 0; q < 4; q++)
                atomicAdd(&g_sumexp[rbase + 8 * q], rs[q]);
        }

        __syncthreads();   // everyone done reading buf[b&1]
        if (b < 2) {
            uint32_t dst = sb + ((b & 1) ? SM_X1 : SM_X0);
#pragma unroll
            for (int it = 0; it < 16; it++) {
                int i = tid + 256 * it, r = i >> 5, cc = i & 31;
                CP16F(dst + tile_off(r, cc),
                      xsrc + ((size_t)((b + 2) * 128 + r) * 32 + cc) * 16);
            }
            CP_COMMIT();
            CP_WAIT1();
        } else if (b == 2) {
            CP_WAIT0();
        }
        __syncthreads();
    }

    // ---- fused finalize: last CTA computes the loss ----
    __threadfence();
    __shared__ int is_last;
    if (tid == 0)
        is_last = (atomicAdd(&g_done, 1u) == (unsigned)(gridDim.x - 1));
    __syncthreads();
    if (is_last) {
        __shared__ double red[256];
        double a = 0.0;
#pragma unroll
        for (int k = 0; k < 2; k++) {
            int b = tid + 256 * k;
            float ct = g_cost[b];
            float lt = S_SCALE * (ct - MARGIN);
            float s = g_sumexp[b] - (float)npad * expf(-30.0f)
                    + __expf(lt - 30.0f) - __expf(S_SCALE * ct - 30.0f);
            a += (double)(30.0f + logf(s) - lt);
        }
        red[tid] = a;
        __syncthreads();
        for (int o = 128; o; o >>= 1) {
            if (tid < o) red[tid] += red[tid + o];
            __syncthreads();
        }
        if (tid == 0) out[0] = (float)(red[0] / (double)BB);
    }
}

// ---------------------------------------------------------
extern "C" void kernel_launch(void* const* d_in, const int* in_sizes, int n_in,
                              void* d_out, int out_size) {
    const float* inputs  = (const float*)d_in[0];
    const float* weight  = (const float*)d_in[1];
    const int*   targets = (const int*)d_in[2];
    float* out = (float*)d_out;

    int C = in_sizes[1] / DD;
    int gridC = (C + 127) / 128;
    int npad = gridC * 128 - C;

    cudaFuncSetAttribute(gemm_sumexp_kernel,
                         cudaFuncAttributeMaxDynamicSharedMemorySize, SM_TOTAL);

    prep_cost_kernel<<<128, 256>>>(inputs, weight, targets);
    gemm_sumexp_kernel<<<gridC, 256, SM_TOTAL>>>(weight, out, C, npad);
}

// round 14
// speedup vs baseline: 1.3481x; 1.1312x over previous
#include <cuda_runtime.h>
#include <cuda_fp16.h>
#include <cstdint>

#define BB 512
#define DD 256
#define CC_MAX 200000
#define S_SCALE 30.0f
#define MARGIN 0.2f
#define EXPC 43.2808512f          // 30 * log2(e)

// -------- device scratch --------
__device__ __half g_wn[(size_t)CC_MAX * DD];  // normalized W, fp16
__device__ __half g_xn[BB * DD];              // normalized X, fp16
__device__ float g_sumexp[BB];
__device__ float g_cost[BB];

// ---------------- helpers ----------------
__device__ __forceinline__ uint32_t smem_u32(const void* p) {
    uint32_t a;
    asm("{ .reg .u64 t; cvta.to.shared.u64 t, %1; cvt.u32.u64 %0, t; }"
        : "=r"(a) : "l"(p));
    return a;
}

#define CP16(sa, ga, sz) \
    asm volatile("cp.async.cg.shared.global [%0], [%1], 16, %2;" \
                 :: "r"(sa), "l"(ga), "r"(sz) : "memory")
#define CP16F(sa, ga) \
    asm volatile("cp.async.cg.shared.global [%0], [%1], 16;" \
                 :: "r"(sa), "l"(ga) : "memory")
#define CP_COMMIT() asm volatile("cp.async.commit_group;" ::: "memory")
#define CP_WAIT1()  asm volatile("cp.async.wait_group 1;" ::: "memory")
#define CP_WAIT0()  asm volatile("cp.async.wait_group 0;" ::: "memory")

#define LDSM4(r0, r1, r2, r3, addr) \
    asm volatile("ldmatrix.sync.aligned.m8n8.x4.shared.b16 {%0,%1,%2,%3}, [%4];" \
                 : "=r"(r0), "=r"(r1), "=r"(r2), "=r"(r3) : "r"(addr))

// fp16-accumulator HMMA
__device__ __forceinline__ void mma16816h(uint32_t* d, const uint32_t* a,
                                          uint32_t b0, uint32_t b1) {
    asm volatile(
        "mma.sync.aligned.m16n8k16.row.col.f16.f16.f16.f16 "
        "{%0,%1}, {%2,%3,%4,%5}, {%6,%7}, {%0,%1};\n"
        : "+r"(d[0]), "+r"(d[1])
        : "r"(a[0]), "r"(a[1]), "r"(a[2]), "r"(a[3]), "r"(b0), "r"(b1));
}

__device__ __forceinline__ uint32_t pack_h2(float x, float y) {
    __half2 h = __floats2half2_rn(x, y);
    return *reinterpret_cast<uint32_t*>(&h);
}
__device__ __forceinline__ float2 h2_to_f2(uint32_t u) {
    __half2 h;
    *reinterpret_cast<uint32_t*>(&h) = u;
    return __half22float2(h);
}

// SW128 blocked-atom tile: 128 rows x 256 fp16 (32 chunks of 16B per row).
__device__ __forceinline__ uint32_t tile_off(int r, int cc) {
    return (uint32_t)(((r >> 3) + (cc >> 3) * 16) * 1024
                    + (r & 7) * 128 + ((((cc & 7) * 16) ^ ((r & 7) << 4))));
}

// ---------------------------------------------------------
// merged prep: blocks 0-63 normalize X (8 rows each; block 0 zeros accums);
// blocks 64-127 compute exact fp32 target cosines (local dtype decode).
__global__ void prep_cost_kernel(const float* __restrict__ in,
                                 const float* __restrict__ W,
                                 const int* __restrict__ t32) {
    int wid = threadIdx.x >> 5, lane = threadIdx.x & 31;
    if (blockIdx.x < 64) {
        if (blockIdx.x == 0) {
            int i = threadIdx.x;
            g_sumexp[i] = 0.0f;
            g_sumexp[i + 256] = 0.0f;
        }
        int row = blockIdx.x * 8 + wid;
        const float4* p = (const float4*)(in + (size_t)row * DD);
        float4 v0 = p[lane];
        float4 v1 = p[lane + 32];
        float s = v0.x * v0.x + v0.y * v0.y + v0.z * v0.z + v0.w * v0.w
                + v1.x * v1.x + v1.y * v1.y + v1.z * v1.z + v1.w * v1.w;
#pragma unroll
        for (int o = 16; o; o >>= 1) s += __shfl_xor_sync(0xffffffffu, s, o);
        float inv = rsqrtf(s);
        unsigned* q = (unsigned*)(g_xn + (size_t)row * DD);
        q[2 * lane + 0]        = pack_h2(v0.x * inv, v0.y * inv);
        q[2 * lane + 1]        = pack_h2(v0.z * inv, v0.w * inv);
        q[2 * (lane + 32) + 0] = pack_h2(v1.x * inv, v1.y * inv);
        q[2 * (lane + 32) + 1] = pack_h2(v1.z * inv, v1.w * inv);
    } else {
        // dtype decode: int64 little-endian => odd 32-bit words all zero
        __shared__ int flag;
        if (threadIdx.x == 0) flag = 0;
        __syncthreads();
        if (t32[2 * threadIdx.x + 1] != 0) flag = 1;   // racy OR, fine
        __syncthreads();
        int b = (blockIdx.x - 64) * 8 + wid;
        int c = flag ? t32[b] : (int)((const long long*)t32)[b];
        const float4* wr = (const float4*)(W + (size_t)c * DD);
        const float4* xr = (const float4*)(in + (size_t)b * DD);
        float dxx = 0.f, dww = 0.f, dxw = 0.f;
#pragma unroll
        for (int h = 0; h < 2; h++) {
            float4 w = wr[lane + 32 * h];
            float4 x = xr[lane + 32 * h];
            dww += w.x * w.x + w.y * w.y + w.z * w.z + w.w * w.w;
            dxx += x.x * x.x + x.y * x.y + x.z * x.z + x.w * x.w;
            dxw += w.x * x.x + w.y * x.y + w.z * x.z + w.w * x.w;
        }
#pragma unroll
        for (int o = 16; o; o >>= 1) {
            dxx += __shfl_xor_sync(0xffffffffu, dxx, o);
            dww += __shfl_xor_sync(0xffffffffu, dww, o);
            dxw += __shfl_xor_sync(0xffffffffu, dxw, o);
        }
        if (lane == 0) g_cost[b] = dxw * rsqrtf(dxx * dww);
    }
}

// ---------------------------------------------------------
// normalize W rows -> fp16 g_wn (one warp per row; DRAM-bound)
__global__ void norm_w_kernel(const float* __restrict__ W, int C) {
    int row = blockIdx.x * 8 + (threadIdx.x >> 5);
    if (row >= C) return;
    int lane = threadIdx.x & 31;
    const float4* p = (const float4*)(W + (size_t)row * DD);
    float4 v0 = p[lane];
    float4 v1 = p[lane + 32];
    float s = v0.x * v0.x + v0.y * v0.y + v0.z * v0.z + v0.w * v0.w
            + v1.x * v1.x + v1.y * v1.y + v1.z * v1.z + v1.w * v1.w;
#pragma unroll
    for (int o = 16; o; o >>= 1) s += __shfl_xor_sync(0xffffffffu, s, o);
    float inv = rsqrtf(s);
    unsigned* q = (unsigned*)(g_wn + (size_t)row * DD);
    q[2 * lane + 0]        = pack_h2(v0.x * inv, v0.y * inv);
    q[2 * lane + 1]        = pack_h2(v0.z * inv, v0.w * inv);
    q[2 * (lane + 32) + 0] = pack_h2(v1.x * inv, v1.y * inv);
    q[2 * (lane + 32) + 1] = pack_h2(v1.z * inv, v1.w * inv);
}

// ---------------------------------------------------------
// GEMM + exp-sum: pure cp.async-fed mainloop (R4 skeleton, fp16/f16-acc).
#define SM_W   0
#define SM_X0  65536
#define SM_X1  131072
#define SM_TOTAL 196608

__global__ __launch_bounds__(256, 1) void gemm_sumexp_kernel(int C) {
    extern __shared__ char smem[];
    const uint32_t sb = smem_u32(smem);
    const int tid = threadIdx.x, wid = tid >> 5, lane = tid & 31;
    const int cbase = blockIdx.x * 128;
    const char* wsrc = (const char*)g_wn;
    const char* xsrc = (const char*)g_xn;

    // prologue: W tile (zero-fill past C) + X0 in group 0; X1 in group 1
#pragma unroll
    for (int it = 0; it < 16; it++) {
        int i = tid + 256 * it, r = i >> 5, cc = i & 31;
        int cg = cbase + r;
        int ok = (cg < C);
        const char* ga = wsrc + ((size_t)(ok ? cg : 0) * 32 + cc) * 16;
        CP16(sb + SM_W + tile_off(r, cc), ga, ok ? 16 : 0);
    }
#pragma unroll
    for (int it = 0; it < 16; it++) {
        int i = tid + 256 * it, r = i >> 5, cc = i & 31;
        CP16F(sb + SM_X0 + tile_off(r, cc), xsrc + ((size_t)r * 32 + cc) * 16);
    }
    CP_COMMIT();
#pragma unroll
    for (int it = 0; it < 16; it++) {
        int i = tid + 256 * it, r = i >> 5, cc = i & 31;
        CP16F(sb + SM_X1 + tile_off(r, cc), xsrc + ((size_t)(128 + r) * 32 + cc) * 16);
    }
    CP_COMMIT();
    CP_WAIT1();        // W + X0 resident; X1 in flight
    __syncthreads();

    const int wm = wid & 3, wn = wid >> 2;
    const int m0 = wm * 32, n0 = wn * 64;
    const int a_rl   = ((lane >> 3) & 1) * 8 + (lane & 7);
    const int a_cchi = (lane >> 4) & 1;
    const int b_rl   = ((lane >> 4) & 1) * 8 + (lane & 7);
    const int b_cchi = (lane >> 3) & 1;
    const uint32_t wa = sb + SM_W;

    for (int b = 0; b < 4; b++) {
        const uint32_t xa = sb + ((b & 1) ? SM_X1 : SM_X0);

        uint32_t acc[2][8][2];   // fp16x2 accumulators
#pragma unroll
        for (int i = 0; i < 2; i++)
#pragma unroll
            for (int j = 0; j < 8; j++) {
                acc[i][j][0] = 0u;
                acc[i][j][1] = 0u;
            }

#pragma unroll
        for (int s = 0; s < 16; s++) {
            uint32_t afr[2][4];
#pragma unroll
            for (int i = 0; i < 2; i++) {
                int r = m0 + 16 * i + a_rl, cc = 2 * s + a_cchi;
                LDSM4(afr[i][0], afr[i][1], afr[i][2], afr[i][3],
                      xa + tile_off(r, cc));
            }
            uint32_t bfr[4][4];
#pragma unroll
            for (int j4 = 0; j4 < 4; j4++) {
                int r = n0 + 16 * j4 + b_rl, cc = 2 * s + b_cchi;
                LDSM4(bfr[j4][0], bfr[j4][1], bfr[j4][2], bfr[j4][3],
                      wa + tile_off(r, cc));
            }
#pragma unroll
            for (int j = 0; j < 8; j++) {
                uint32_t b0 = bfr[j >> 1][(j & 1) * 2];
                uint32_t b1 = bfr[j >> 1][(j & 1) * 2 + 1];
                mma16816h(acc[0][j], afr[0], b0, b1);
                mma16816h(acc[1][j], afr[1], b0, b1);
            }
        }

        // epilogue: unpack fp16 pairs, exp2, per-row reduce
        float rs[4] = {0.f, 0.f, 0.f, 0.f};
#pragma unroll
        for (int i = 0; i < 2; i++)
#pragma unroll
            for (int j = 0; j < 8; j++) {
                float2 c0 = h2_to_f2(acc[i][j][0]);
                float2 c1 = h2_to_f2(acc[i][j][1]);
                rs[2 * i]     += exp2f(fmaf(EXPC, c0.x, -EXPC))
                               + exp2f(fmaf(EXPC, c0.y, -EXPC));
                rs[2 * i + 1] += exp2f(fmaf(EXPC, c1.x, -EXPC))
                               + exp2f(fmaf(EXPC, c1.y, -EXPC));
            }
#pragma unroll
        for (int q = 0; q < 4; q++) {
            rs[q] += __shfl_xor_sync(0xffffffffu, rs[q], 1);
            rs[q] += __shfl_xor_sync(0xffffffffu, rs[q], 2);
        }
        if ((lane & 3) == 0) {
            int rbase = b * 128 + m0 + (lane >> 2);
#pragma unroll
            for (int q = 0; q < 4; q++)
                atomicAdd(&g_sumexp[rbase + 8 * q], rs[q]);
        }

        __syncthreads();   // everyone done reading buf[b&1]
        if (b < 2) {
            uint32_t dst = sb + ((b & 1) ? SM_X1 : SM_X0);
#pragma unroll
            for (int it = 0; it < 16; it++) {
                int i = tid + 256 * it, r = i >> 5, cc = i & 31;
                CP16F(dst + tile_off(r, cc),
                      xsrc + ((size_t)((b + 2) * 128 + r) * 32 + cc) * 16);
            }
            CP_COMMIT();
            CP_WAIT1();
        } else if (b == 2) {
            CP_WAIT0();
        }
        __syncthreads();
    }
}

// ---------------------------------------------------------
// finalize: pad removal, margin correction (exact cosine), lse, mean
__global__ void finalize_kernel(float* __restrict__ out, int npad) {
    __shared__ double sd[BB];
    int b = threadIdx.x;
    float ct = g_cost[b];
    float lt = S_SCALE * (ct - MARGIN);
    float s = g_sumexp[b] - (float)npad * expf(-30.0f)
            + __expf(lt - 30.0f) - __expf(S_SCALE * ct - 30.0f);
    float nll = 30.0f + logf(s) - lt;
    sd[b] = (double)nll;
    __syncthreads();
    for (int o = 256; o; o >>= 1) {
        if (b < o) sd[b] += sd[b + o];
        __syncthreads();
    }
    if (b == 0) out[0] = (float)(sd[0] / (double)BB);
}

// ---------------------------------------------------------
extern "C" void kernel_launch(void* const* d_in, const int* in_sizes, int n_in,
                              void* d_out, int out_size) {
    const float* inputs  = (const float*)d_in[0];
    const float* weight  = (const float*)d_in[1];
    const int*   targets = (const int*)d_in[2];
    float* out = (float*)d_out;

    int C = in_sizes[1] / DD;
    int gridC = (C + 127) / 128;
    int npad = gridC * 128 - C;

    cudaFuncSetAttribute(gemm_sumexp_kernel,
                         cudaFuncAttributeMaxDynamicSharedMemorySize, SM_TOTAL);

    prep_cost_kernel<<<128, 256>>>(inputs, weight, targets);
    norm_w_kernel<<<(C + 7) / 8, 256>>>(weight, C);
    gemm_sumexp_kernel<<<gridC, 256, SM_TOTAL>>>(C);
    finalize_kernel<<<1, BB>>>(out, npad);
}

// round 15
// speedup vs baseline: 1.3735x; 1.0188x over previous
#include <cuda_runtime.h>
#include <cuda_fp16.h>
#include <cstdint>

#define BB 512
#define DD 256
#define CC_MAX 200000
#define S_SCALE 30.0f
#define MARGIN 0.2f
#define EXPC 43.2808512f          // 30 * log2(e)

// -------- device scratch --------
__device__ __half g_wn[(size_t)CC_MAX * DD];  // normalized W, fp16
__device__ __half g_xn[BB * DD];              // normalized X, fp16
__device__ float g_sumexp[BB];
__device__ float g_cost[BB];

// ---------------- helpers ----------------
__device__ __forceinline__ uint32_t smem_u32(const void* p) {
    uint32_t a;
    asm("{ .reg .u64 t; cvta.to.shared.u64 t, %1; cvt.u32.u64 %0, t; }"
        : "=r"(a) : "l"(p));
    return a;
}

#define CP16(sa, ga, sz) \
    asm volatile("cp.async.cg.shared.global [%0], [%1], 16, %2;" \
                 :: "r"(sa), "l"(ga), "r"(sz) : "memory")
#define CP16F(sa, ga) \
    asm volatile("cp.async.cg.shared.global [%0], [%1], 16;" \
                 :: "r"(sa), "l"(ga) : "memory")
#define CP_COMMIT() asm volatile("cp.async.commit_group;" ::: "memory")
#define CP_WAIT1()  asm volatile("cp.async.wait_group 1;" ::: "memory")
#define CP_WAIT0()  asm volatile("cp.async.wait_group 0;" ::: "memory")

#define LDSM4(r0, r1, r2, r3, addr) \
    asm volatile("ldmatrix.sync.aligned.m8n8.x4.shared.b16 {%0,%1,%2,%3}, [%4];" \
                 : "=r"(r0), "=r"(r1), "=r"(r2), "=r"(r3) : "r"(addr))

// fp16-accumulator HMMA
__device__ __forceinline__ void mma16816h(uint32_t* d, const uint32_t* a,
                                          uint32_t b0, uint32_t b1) {
    asm volatile(
        "mma.sync.aligned.m16n8k16.row.col.f16.f16.f16.f16 "
        "{%0,%1}, {%2,%3,%4,%5}, {%6,%7}, {%0,%1};\n"
        : "+r"(d[0]), "+r"(d[1])
        : "r"(a[0]), "r"(a[1]), "r"(a[2]), "r"(a[3]), "r"(b0), "r"(b1));
}

__device__ __forceinline__ uint32_t pack_h2(float x, float y) {
    __half2 h = __floats2half2_rn(x, y);
    return *reinterpret_cast<uint32_t*>(&h);
}
__device__ __forceinline__ float2 h2_to_f2(uint32_t u) {
    __half2 h;
    *reinterpret_cast<uint32_t*>(&h) = u;
    return __half22float2(h);
}

// SW128 blocked-atom tile: 128 rows x 256 fp16 (32 chunks of 16B per row).
__device__ __forceinline__ uint32_t tile_off(int r, int cc) {
    return (uint32_t)(((r >> 3) + (cc >> 3) * 16) * 1024
                    + (r & 7) * 128 + ((((cc & 7) * 16) ^ ((r & 7) << 4))));
}

// row-normalize a [DD] fp32 row -> fp16 (one warp)
__device__ __forceinline__ void norm_row_to_h2(const float* __restrict__ src,
                                               __half* __restrict__ dst,
                                               int lane) {
    const float4* p = (const float4*)src;
    float4 v0 = p[lane];
    float4 v1 = p[lane + 32];
    float s = v0.x * v0.x + v0.y * v0.y + v0.z * v0.z + v0.w * v0.w
            + v1.x * v1.x + v1.y * v1.y + v1.z * v1.z + v1.w * v1.w;
#pragma unroll
    for (int o = 16; o; o >>= 1) s += __shfl_xor_sync(0xffffffffu, s, o);
    float inv = rsqrtf(s);
    unsigned* q = (unsigned*)dst;
    q[2 * lane + 0]        = pack_h2(v0.x * inv, v0.y * inv);
    q[2 * lane + 1]        = pack_h2(v0.z * inv, v0.w * inv);
    q[2 * (lane + 32) + 0] = pack_h2(v1.x * inv, v1.y * inv);
    q[2 * (lane + 32) + 1] = pack_h2(v1.z * inv, v1.w * inv);
}

// ---------------------------------------------------------
// merged prep:
//   blocks [0,64)    : X normalize (8 rows each; block 0 zeros accums)
//   blocks [64,128)  : exact fp32 target cosines (local dtype decode)
//   blocks [128,...) : W normalize in REVERSE tile order so the tiles the
//                      GEMM reads first are the last written (L2-warm)
__global__ void prep_all_kernel(const float* __restrict__ in,
                                const float* __restrict__ W,
                                const int* __restrict__ t32, int C) {
    int wid = threadIdx.x >> 5, lane = threadIdx.x & 31;
    if (blockIdx.x < 64) {
        if (blockIdx.x == 0) {
            int i = threadIdx.x;
            g_sumexp[i] = 0.0f;
            g_sumexp[i + 256] = 0.0f;
        }
        int row = blockIdx.x * 8 + wid;
        norm_row_to_h2(in + (size_t)row * DD, g_xn + (size_t)row * DD, lane);
    } else if (blockIdx.x < 128) {
        // dtype decode: int64 little-endian => odd 32-bit words all zero
        __shared__ int flag;
        if (threadIdx.x == 0) flag = 0;
        __syncthreads();
        if (t32[2 * threadIdx.x + 1] != 0) flag = 1;   // racy OR, fine
        __syncthreads();
        int b = (blockIdx.x - 64) * 8 + wid;
        int c = flag ? t32[b] : (int)((const long long*)t32)[b];
        const float4* wr = (const float4*)(W + (size_t)c * DD);
        const float4* xr = (const float4*)(in + (size_t)b * DD);
        float dxx = 0.f, dww = 0.f, dxw = 0.f;
#pragma unroll
        for (int h = 0; h < 2; h++) {
            float4 w = wr[lane + 32 * h];
            float4 x = xr[lane + 32 * h];
            dww += w.x * w.x + w.y * w.y + w.z * w.z + w.w * w.w;
            dxx += x.x * x.x + x.y * x.y + x.z * x.z + x.w * x.w;
            dxw += w.x * x.x + w.y * x.y + w.z * x.z + w.w * x.w;
        }
#pragma unroll
        for (int o = 16; o; o >>= 1) {
            dxx += __shfl_xor_sync(0xffffffffu, dxx, o);
            dww += __shfl_xor_sync(0xffffffffu, dww, o);
            dxw += __shfl_xor_sync(0xffffffffu, dxw, o);
        }
        if (lane == 0) g_cost[b] = dxw * rsqrtf(dxx * dww);
    } else {
        // W normalize, reverse order: block j covers rows [C-8(j+1), C-8j)
        int j = blockIdx.x - 128;
        int row = C - 8 * (j + 1) + wid;
        if (row >= 0 && row < C)
            norm_row_to_h2(W + (size_t)row * DD, g_wn + (size_t)row * DD, lane);
    }
}

// ---------------------------------------------------------
// GEMM + exp-sum: pure cp.async-fed mainloop (fp16 in / fp16 acc).
#define SM_W   0
#define SM_X0  65536
#define SM_X1  131072
#define SM_TOTAL 196608

__global__ __launch_bounds__(256, 1) void gemm_sumexp_kernel(int C) {
    extern __shared__ char smem[];
    const uint32_t sb = smem_u32(smem);
    const int tid = threadIdx.x, wid = tid >> 5, lane = tid & 31;
    const int cbase = blockIdx.x * 128;
    const char* wsrc = (const char*)g_wn;
    const char* xsrc = (const char*)g_xn;

    // prologue: W tile (zero-fill past C) + X0 in group 0; X1 in group 1
#pragma unroll
    for (int it = 0; it < 16; it++) {
        int i = tid + 256 * it, r = i >> 5, cc = i & 31;
        int cg = cbase + r;
        int ok = (cg < C);
        const char* ga = wsrc + ((size_t)(ok ? cg : 0) * 32 + cc) * 16;
        CP16(sb + SM_W + tile_off(r, cc), ga, ok ? 16 : 0);
    }
#pragma unroll
    for (int it = 0; it < 16; it++) {
        int i = tid + 256 * it, r = i >> 5, cc = i & 31;
        CP16F(sb + SM_X0 + tile_off(r, cc), xsrc + ((size_t)r * 32 + cc) * 16);
    }
    CP_COMMIT();
#pragma unroll
    for (int it = 0; it < 16; it++) {
        int i = tid + 256 * it, r = i >> 5, cc = i & 31;
        CP16F(sb + SM_X1 + tile_off(r, cc), xsrc + ((size_t)(128 + r) * 32 + cc) * 16);
    }
    CP_COMMIT();
    CP_WAIT1();        // W + X0 resident; X1 in flight
    __syncthreads();

    const int wm = wid & 3, wn = wid >> 2;
    const int m0 = wm * 32, n0 = wn * 64;
    const int a_rl   = ((lane >> 3) & 1) * 8 + (lane & 7);
    const int a_cchi = (lane >> 4) & 1;
    const int b_rl   = ((lane >> 4) & 1) * 8 + (lane & 7);
    const int b_cchi = (lane >> 3) & 1;
    const uint32_t wa = sb + SM_W;

    for (int b = 0; b < 4; b++) {
        const uint32_t xa = sb + ((b & 1) ? SM_X1 : SM_X0);

        uint32_t acc[2][8][2];   // fp16x2 accumulators
#pragma unroll
        for (int i = 0; i < 2; i++)
#pragma unroll
            for (int j = 0; j < 8; j++) {
                acc[i][j][0] = 0u;
                acc[i][j][1] = 0u;
            }

#pragma unroll
        for (int s = 0; s < 16; s++) {
            uint32_t afr[2][4];
#pragma unroll
            for (int i = 0; i < 2; i++) {
                int r = m0 + 16 * i + a_rl, cc = 2 * s + a_cchi;
                LDSM4(afr[i][0], afr[i][1], afr[i][2], afr[i][3],
                      xa + tile_off(r, cc));
            }
            uint32_t bfr[4][4];
#pragma unroll
            for (int j4 = 0; j4 < 4; j4++) {
                int r = n0 + 16 * j4 + b_rl, cc = 2 * s + b_cchi;
                LDSM4(bfr[j4][0], bfr[j4][1], bfr[j4][2], bfr[j4][3],
                      wa + tile_off(r, cc));
            }
#pragma unroll
            for (int j = 0; j < 8; j++) {
                uint32_t b0 = bfr[j >> 1][(j & 1) * 2];
                uint32_t b1 = bfr[j >> 1][(j & 1) * 2 + 1];
                mma16816h(acc[0][j], afr[0], b0, b1);
                mma16816h(acc[1][j], afr[1], b0, b1);
            }
        }

        // epilogue: unpack fp16 pairs, exp2, per-row reduce
        float rs[4] = {0.f, 0.f, 0.f, 0.f};
#pragma unroll
        for (int i = 0; i < 2; i++)
#pragma unroll
            for (int j = 0; j < 8; j++) {
                float2 c0 = h2_to_f2(acc[i][j][0]);
                float2 c1 = h2_to_f2(acc[i][j][1]);
                rs[2 * i]     += exp2f(fmaf(EXPC, c0.x, -EXPC))
                               + exp2f(fmaf(EXPC, c0.y, -EXPC));
                rs[2 * i + 1] += exp2f(fmaf(EXPC, c1.x, -EXPC))
                               + exp2f(fmaf(EXPC, c1.y, -EXPC));
            }
#pragma unroll
        for (int q = 0; q < 4; q++) {
            rs[q] += __shfl_xor_sync(0xffffffffu, rs[q], 1);
            rs[q] += __shfl_xor_sync(0xffffffffu, rs[q], 2);
        }
        if ((lane & 3) == 0) {
            int rbase = b * 128 + m0 + (lane >> 2);
#pragma unroll
            for (int q = 0; q < 4; q++)
                atomicAdd(&g_sumexp[rbase + 8 * q], rs[q]);
        }

        __syncthreads();   // everyone done reading buf[b&1]
        if (b < 2) {
            uint32_t dst = sb + ((b & 1) ? SM_X1 : SM_X0);
#pragma unroll
            for (int it = 0; it < 16; it++) {
                int i = tid + 256 * it, r = i >> 5, cc = i & 31;
                CP16F(dst + tile_off(r, cc),
                      xsrc + ((size_t)((b + 2) * 128 + r) * 32 + cc) * 16);
            }
            CP_COMMIT();
            CP_WAIT1();
        } else if (b == 2) {
            CP_WAIT0();
        }
        __syncthreads();
    }
}

// ---------------------------------------------------------
// finalize: pad removal, margin correction (exact cosine), lse, mean
__global__ void finalize_kernel(float* __restrict__ out, int npad) {
    __shared__ double sd[BB];
    int b = threadIdx.x;
    float ct = g_cost[b];
    float lt = S_SCALE * (ct - MARGIN);
    float s = g_sumexp[b] - (float)npad * expf(-30.0f)
            + __expf(lt - 30.0f) - __expf(S_SCALE * ct - 30.0f);
    float nll = 30.0f + logf(s) - lt;
    sd[b] = (double)nll;
    __syncthreads();
    for (int o = 256; o; o >>= 1) {
        if (b < o) sd[b] += sd[b + o];
        __syncthreads();
    }
    if (b == 0) out[0] = (float)(sd[0] / (double)BB);
}

// ---------------------------------------------------------
extern "C" void kernel_launch(void* const* d_in, const int* in_sizes, int n_in,
                              void* d_out, int out_size) {
    const float* inputs  = (const float*)d_in[0];
    const float* weight  = (const float*)d_in[1];
    const int*   targets = (const int*)d_in[2];
    float* out = (float*)d_out;

    int C = in_sizes[1] / DD;
    int gridC = (C + 127) / 128;
    int npad = gridC * 128 - C;
    int prep_grid = 128 + (C + 7) / 8;

    cudaFuncSetAttribute(gemm_sumexp_kernel,
                         cudaFuncAttributeMaxDynamicSharedMemorySize, SM_TOTAL);

    prep_all_kernel<<<prep_grid, 256>>>(inputs, weight, targets, C);
    gemm_sumexp_kernel<<<gridC, 256, SM_TOTAL>>>(C);
    finalize_kernel<<<1, BB>>>(out, npad);
}